// round 7
// baseline (speedup 1.0000x reference)
#include <cuda_runtime.h>
#include <cuda_fp16.h>

// ---------------------------------------------------------------------------
// GCN link prediction, CSR-gather formulation:
//   hs = (x@W)*dinv (fp16) -> acc[c] = hs[c] + sum_{dst=c} hs[src]
//   out[c] = dinv[c]*acc[c] + b  (relu layer 1 -> fp32; layer 2 -> fp16 z)
// CSR build: count records per-edge rank (atomicAdd return) as u16; place is
// atomic-free: esrc[rowptr[dst]+rank] = (u16)src. Node ids < 50000 fit u16.
// ---------------------------------------------------------------------------

#define N_NODES 50000
#define E_TRAIN 1600000
#define EP      200000
#define EN      200000
#define F_IN    50
#define HID     50
#define DOUT    64
#define PAD     64

__device__ __align__(256) __half g_bufA[N_NODES * PAD]; // hs fp16 (gather src)
__device__ __align__(256) float  g_bufC[N_NODES * PAD]; // layer-1 output (fp32)
__device__ __align__(256) __half g_z[N_NODES * PAD];    // layer-2 output (fp16)
__device__ int   g_deg[N_NODES];
__device__ int   g_rowptr[N_NODES + 1];
__device__ __align__(16) unsigned short g_rank[E_TRAIN];
__device__ __align__(16) unsigned short g_esrc[E_TRAIN];
__device__ float g_dinv[N_NODES];

// ---- degree + rank (8 edges/thread) -----------------------------------------
__global__ void k_zero() {
    int i = blockIdx.x * blockDim.x + threadIdx.x;
    if (i < N_NODES) g_deg[i] = 0;
}

__global__ void k_count(const int* __restrict__ dst) {
    int t = blockIdx.x * 256 + threadIdx.x;
    if (t < E_TRAIN / 8) {
        int4 d0 = __ldg((const int4*)dst + 2 * t);
        int4 d1 = __ldg((const int4*)dst + 2 * t + 1);
        unsigned r0 = atomicAdd(&g_deg[d0.x], 1);
        unsigned r1 = atomicAdd(&g_deg[d0.y], 1);
        unsigned r2 = atomicAdd(&g_deg[d0.z], 1);
        unsigned r3 = atomicAdd(&g_deg[d0.w], 1);
        unsigned r4 = atomicAdd(&g_deg[d1.x], 1);
        unsigned r5 = atomicAdd(&g_deg[d1.y], 1);
        unsigned r6 = atomicAdd(&g_deg[d1.z], 1);
        unsigned r7 = atomicAdd(&g_deg[d1.w], 1);
        uint4 pk;
        pk.x = r0 | (r1 << 16);
        pk.y = r2 | (r3 << 16);
        pk.z = r4 | (r5 << 16);
        pk.w = r6 | (r7 << 16);
        ((uint4*)g_rank)[t] = pk;
    }
}

// ---- single-block exclusive scan -> rowptr/dinv -----------------------------
#define SCAN_T 1024
#define CHUNK  49     // 1024*49 = 50176 >= 50000

__global__ __launch_bounds__(SCAN_T) void k_scan() {
    __shared__ int part[SCAN_T];
    int t = threadIdx.x;
    int base = t * CHUNK;
    int s = 0;
#pragma unroll 7
    for (int i = 0; i < CHUNK; i++) {
        int idx = base + i;
        if (idx < N_NODES) s += __ldg(g_deg + idx);
    }
    part[t] = s;
    __syncthreads();
    for (int off = 1; off < SCAN_T; off <<= 1) {
        int v = (t >= off) ? part[t - off] : 0;
        __syncthreads();
        part[t] += v;
        __syncthreads();
    }
    int run = (t > 0) ? part[t - 1] : 0;
    for (int i = 0; i < CHUNK; i++) {
        int idx = base + i;
        if (idx < N_NODES) {
            int d = g_deg[idx];
            g_rowptr[idx] = run;
            g_dinv[idx]   = rsqrtf((float)(d + 1));   // +1 self loop
            run += d;
        }
    }
    if (t == SCAN_T - 1) g_rowptr[N_NODES] = run;
}

// ---- atomic-free placement (8 edges/thread) ---------------------------------
__global__ void k_place(const int* __restrict__ src, const int* __restrict__ dst) {
    int t = blockIdx.x * 256 + threadIdx.x;
    if (t < E_TRAIN / 8) {
        int4 s0 = __ldg((const int4*)src + 2 * t);
        int4 s1 = __ldg((const int4*)src + 2 * t + 1);
        int4 d0 = __ldg((const int4*)dst + 2 * t);
        int4 d1 = __ldg((const int4*)dst + 2 * t + 1);
        uint4 pk = __ldg((const uint4*)g_rank + t);
        int p0 = __ldg(g_rowptr + d0.x) + (pk.x & 0xffff);
        int p1 = __ldg(g_rowptr + d0.y) + (pk.x >> 16);
        int p2 = __ldg(g_rowptr + d0.z) + (pk.y & 0xffff);
        int p3 = __ldg(g_rowptr + d0.w) + (pk.y >> 16);
        int p4 = __ldg(g_rowptr + d1.x) + (pk.z & 0xffff);
        int p5 = __ldg(g_rowptr + d1.y) + (pk.z >> 16);
        int p6 = __ldg(g_rowptr + d1.z) + (pk.w & 0xffff);
        int p7 = __ldg(g_rowptr + d1.w) + (pk.w >> 16);
        g_esrc[p0] = (unsigned short)s0.x;
        g_esrc[p1] = (unsigned short)s0.y;
        g_esrc[p2] = (unsigned short)s0.z;
        g_esrc[p3] = (unsigned short)s0.w;
        g_esrc[p4] = (unsigned short)s1.x;
        g_esrc[p5] = (unsigned short)s1.y;
        g_esrc[p6] = (unsigned short)s1.z;
        g_esrc[p7] = (unsigned short)s1.w;
    }
}

// ---- GEMM 1: bufA = fp16( dinv[i] * (x @ W1) ), W padded to 64 cols --------
__global__ __launch_bounds__(256) void k_gemm1(const float* __restrict__ x,
                                               const float* __restrict__ W1) {
    __shared__ float ws[F_IN][64];
    __shared__ float xs[16][F_IN + 2];
    int tid = threadIdx.x;
    int nodeBase = blockIdx.x * 16;                 // 3125 blocks, always full
    for (int t = tid; t < F_IN * 64; t += 256) {
        int k = t >> 6, j = t & 63;
        ws[k][j] = (j < HID) ? W1[k * HID + j] : 0.f;
    }
    for (int t = tid; t < 16 * F_IN; t += 256) {
        int n = t / F_IN, k = t % F_IN;
        xs[n][k] = x[(nodeBase + n) * F_IN + k];
    }
    __syncthreads();
    int n = tid >> 4, jq = tid & 15;
    int node = nodeBase + n;
    float4 acc = make_float4(0.f, 0.f, 0.f, 0.f);
#pragma unroll
    for (int k = 0; k < F_IN; k++) {
        float xv = xs[n][k];
        float4 w = *(const float4*)&ws[k][jq * 4];
        acc.x = fmaf(xv, w.x, acc.x);
        acc.y = fmaf(xv, w.y, acc.y);
        acc.z = fmaf(xv, w.z, acc.z);
        acc.w = fmaf(xv, w.w, acc.w);
    }
    float di = g_dinv[node];
    __half2 p0 = __floats2half2_rn(acc.x * di, acc.y * di);
    __half2 p1 = __floats2half2_rn(acc.z * di, acc.w * di);
    uint2 st;
    st.x = *(unsigned*)&p0;
    st.y = *(unsigned*)&p1;
    *(uint2*)&g_bufA[node * PAD + jq * 4] = st;
}

// ---- GEMM 2: bufA = fp16( dinv[i] * (bufC @ W2) ) ---------------------------
__global__ __launch_bounds__(256) void k_gemm2(const float* __restrict__ W2) {
    __shared__ float ws[HID][64];
    __shared__ float xs[16][HID + 2];
    int tid = threadIdx.x;
    int nodeBase = blockIdx.x * 16;
    for (int t = tid; t < HID * 64; t += 256) {
        int k = t >> 6, j = t & 63;
        ws[k][j] = W2[k * DOUT + j];
    }
    for (int t = tid; t < 16 * HID; t += 256) {
        int n = t / HID, k = t % HID;
        xs[n][k] = g_bufC[(nodeBase + n) * PAD + k];
    }
    __syncthreads();
    int n = tid >> 4, jq = tid & 15;
    int node = nodeBase + n;
    float4 acc = make_float4(0.f, 0.f, 0.f, 0.f);
#pragma unroll
    for (int k = 0; k < HID; k++) {
        float xv = xs[n][k];
        float4 w = *(const float4*)&ws[k][jq * 4];
        acc.x = fmaf(xv, w.x, acc.x);
        acc.y = fmaf(xv, w.y, acc.y);
        acc.z = fmaf(xv, w.z, acc.z);
        acc.w = fmaf(xv, w.w, acc.w);
    }
    float di = g_dinv[node];
    __half2 p0 = __floats2half2_rn(acc.x * di, acc.y * di);
    __half2 p1 = __floats2half2_rn(acc.z * di, acc.w * di);
    uint2 st;
    st.x = *(unsigned*)&p0;
    st.y = *(unsigned*)&p1;
    *(uint2*)&g_bufA[node * PAD + jq * 4] = st;
}

// ---- CSR aggregation + fused epilogue ---------------------------------------
// One warp per node. 4 edge-groups of 8 lanes; lane q owns 16B chunk q
// (8 halves). CH = active chunks (7 for layer 1). Unroll 8 row-loads in flight.
// FINAL=false: fp32 store to g_bufC (+relu). FINAL=true: fp16 store to g_z.
template <int CH, int NB, bool RELU, bool FINAL>
__global__ __launch_bounds__(256) void k_agg(const float* __restrict__ bias) {
    int node = (blockIdx.x * 256 + threadIdx.x) >> 5;   // 6250 blocks exact
    int lane = threadIdx.x & 31;
    int g = lane >> 3, q = lane & 7;
    int rp = g_rowptr[node], re = g_rowptr[node + 1];
    float a0 = 0.f, a1 = 0.f, a2 = 0.f, a3 = 0.f;
    float a4 = 0.f, a5 = 0.f, a6 = 0.f, a7 = 0.f;
    const uint4* rows = (const uint4*)g_bufA;           // 8 uint4 per row
    const bool act = (CH == 8) || (q < CH);

#define ACCUM(U) do {                                                   \
        __half2* hp = (__half2*)&(U);                                   \
        float2 f0 = __half22float2(hp[0]);                              \
        float2 f1 = __half22float2(hp[1]);                              \
        float2 f2 = __half22float2(hp[2]);                              \
        float2 f3 = __half22float2(hp[3]);                              \
        a0 += f0.x; a1 += f0.y; a2 += f1.x; a3 += f1.y;                 \
        a4 += f2.x; a5 += f2.y; a6 += f3.x; a7 += f3.y;                 \
    } while (0)

    if (g == 0 && act) {                                // self loop
        uint4 u = __ldg(rows + node * 8 + q);
        ACCUM(u);
    }
    int e = rp + g;
    for (; e + 28 < re; e += 32) {
        int s0 = (int)__ldg(g_esrc + e);
        int s1 = (int)__ldg(g_esrc + e + 4);
        int s2 = (int)__ldg(g_esrc + e + 8);
        int s3 = (int)__ldg(g_esrc + e + 12);
        int s4 = (int)__ldg(g_esrc + e + 16);
        int s5 = (int)__ldg(g_esrc + e + 20);
        int s6 = (int)__ldg(g_esrc + e + 24);
        int s7 = (int)__ldg(g_esrc + e + 28);
        if (act) {
            uint4 u0 = __ldg(rows + s0 * 8 + q);
            uint4 u1 = __ldg(rows + s1 * 8 + q);
            uint4 u2 = __ldg(rows + s2 * 8 + q);
            uint4 u3 = __ldg(rows + s3 * 8 + q);
            uint4 u4 = __ldg(rows + s4 * 8 + q);
            uint4 u5 = __ldg(rows + s5 * 8 + q);
            uint4 u6 = __ldg(rows + s6 * 8 + q);
            uint4 u7 = __ldg(rows + s7 * 8 + q);
            ACCUM(u0); ACCUM(u1); ACCUM(u2); ACCUM(u3);
            ACCUM(u4); ACCUM(u5); ACCUM(u6); ACCUM(u7);
        }
    }
    for (; e + 4 < re; e += 8) {
        int s0 = (int)__ldg(g_esrc + e);
        int s1 = (int)__ldg(g_esrc + e + 4);
        if (act) {
            uint4 u0 = __ldg(rows + s0 * 8 + q);
            uint4 u1 = __ldg(rows + s1 * 8 + q);
            ACCUM(u0); ACCUM(u1);
        }
    }
    if (e < re) {
        int s0 = (int)__ldg(g_esrc + e);
        if (act) {
            uint4 u0 = __ldg(rows + s0 * 8 + q);
            ACCUM(u0);
        }
    }
#undef ACCUM

#define RED(off) do {                                                   \
        a0 += __shfl_xor_sync(0xffffffffu, a0, off);                    \
        a1 += __shfl_xor_sync(0xffffffffu, a1, off);                    \
        a2 += __shfl_xor_sync(0xffffffffu, a2, off);                    \
        a3 += __shfl_xor_sync(0xffffffffu, a3, off);                    \
        a4 += __shfl_xor_sync(0xffffffffu, a4, off);                    \
        a5 += __shfl_xor_sync(0xffffffffu, a5, off);                    \
        a6 += __shfl_xor_sync(0xffffffffu, a6, off);                    \
        a7 += __shfl_xor_sync(0xffffffffu, a7, off);                    \
    } while (0)
    RED(8);
    RED(16);
#undef RED

    if (g == 0 && act) {
        float di = g_dinv[node];
        int j0 = q * 8;
        float acc[8] = {a0, a1, a2, a3, a4, a5, a6, a7};
        float v[8];
#pragma unroll
        for (int i = 0; i < 8; i++) {
            int j = j0 + i;
            float bv = (j < NB) ? __ldg(bias + j) : 0.f;
            float r = fmaf(di, acc[i], bv);
            if (RELU) r = fmaxf(r, 0.f);
            v[i] = r;
        }
        if (FINAL) {
            __half2 h0 = __floats2half2_rn(v[0], v[1]);
            __half2 h1 = __floats2half2_rn(v[2], v[3]);
            __half2 h2 = __floats2half2_rn(v[4], v[5]);
            __half2 h3 = __floats2half2_rn(v[6], v[7]);
            uint4 st;
            st.x = *(unsigned*)&h0; st.y = *(unsigned*)&h1;
            st.z = *(unsigned*)&h2; st.w = *(unsigned*)&h3;
            *(uint4*)&g_z[node * PAD + j0] = st;
        } else {
            float4 r0 = make_float4(v[0], v[1], v[2], v[3]);
            float4 r1 = make_float4(v[4], v[5], v[6], v[7]);
            *(float4*)(g_bufC + node * PAD + j0)     = r0;
            *(float4*)(g_bufC + node * PAD + j0 + 4) = r1;
        }
    }
}

// ---- decode: logits[e] = dot64(z[a], z[b]), z fp16 --------------------------
__global__ void k_decode(const int* __restrict__ pos,
                         const int* __restrict__ neg,
                         float* __restrict__ out) {
    int gt = blockIdx.x * 256 + threadIdx.x;   // 12500 blocks exact
    int e = gt >> 3;
    int j = gt & 7;
    int a, b;
    if (e < EP) { a = pos[e];        b = pos[EP + e]; }
    else        { int e2 = e - EP;  a = neg[e2];     b = neg[EN + e2]; }
    uint4 ua = __ldg((const uint4*)(g_z + a * PAD) + j);
    uint4 ub = __ldg((const uint4*)(g_z + b * PAD) + j);
    __half2* ha = (__half2*)&ua;
    __half2* hb = (__half2*)&ub;
    float s = 0.f;
#pragma unroll
    for (int i = 0; i < 4; i++) {
        float2 fa = __half22float2(ha[i]);
        float2 fb = __half22float2(hb[i]);
        s = fmaf(fa.x, fb.x, s);
        s = fmaf(fa.y, fb.y, s);
    }
#pragma unroll
    for (int o = 4; o; o >>= 1) s += __shfl_xor_sync(0xffffffffu, s, o);
    if (j == 0) out[e] = s;
}

// ---------------------------------------------------------------------------
extern "C" void kernel_launch(void* const* d_in, const int* in_sizes, int n_in,
                              void* d_out, int out_size) {
    const float* x   = (const float*)d_in[0];
    const int*   tr  = (const int*)d_in[1];
    const int*   pos = (const int*)d_in[2];
    const int*   neg = (const int*)d_in[3];
    const float* W1  = (const float*)d_in[4];
    const float* b1  = (const float*)d_in[5];
    const float* W2  = (const float*)d_in[6];
    const float* b2  = (const float*)d_in[7];
    float* out = (float*)d_out;

    const int* src = tr;
    const int* dst = tr + E_TRAIN;

    // CSR build
    k_zero<<<(N_NODES + 255) / 256, 256>>>();
    k_count<<<(E_TRAIN / 8 + 255) / 256, 256>>>(dst);
    k_scan<<<1, SCAN_T>>>();
    k_place<<<(E_TRAIN / 8 + 255) / 256, 256>>>(src, dst);

    // layer 1
    k_gemm1<<<N_NODES / 16, 256>>>(x, W1);
    k_agg<7, HID, true, false><<<N_NODES * 32 / 256, 256>>>(b1);

    // layer 2
    k_gemm2<<<N_NODES / 16, 256>>>(W2);
    k_agg<8, DOUT, false, true><<<N_NODES * 32 / 256, 256>>>(b2);

    // decode
    k_decode<<<(EP + EN) * 8 / 256, 256>>>(pos, neg, out);
}

// round 8
// speedup vs baseline: 1.0312x; 1.0312x over previous
#include <cuda_runtime.h>
#include <cuda_fp16.h>

// ---------------------------------------------------------------------------
// GCN link prediction, CSR-gather formulation:
//   hs = (x@W)*dinv (fp16) -> acc[c] = hs[c] + sum_{dst=c} hs[src]
//   out[c] = dinv[c]*acc[c] + b  (relu layer 1 -> fp32; layer 2 -> fp16 z)
// CSR build: count records per-edge rank (atomicAdd return) as u16; place is
// atomic-free: esrc[rowptr[dst]+rank] = (u16)src.
// Streams: gemm1 (stream B) overlaps place (default stream); both depend only
// on scan. Event fork/join keeps the launch graph-capturable.
// ---------------------------------------------------------------------------

#define N_NODES 50000
#define E_TRAIN 1600000
#define EP      200000
#define EN      200000
#define F_IN    50
#define HID     50
#define DOUT    64
#define PAD     64

__device__ __align__(256) __half g_bufA[N_NODES * PAD]; // hs fp16 (gather src)
__device__ __align__(256) float  g_bufC[N_NODES * PAD]; // layer-1 output (fp32)
__device__ __align__(256) __half g_z[N_NODES * PAD];    // layer-2 output (fp16)
__device__ int   g_deg[N_NODES];
__device__ int   g_rowptr[N_NODES + 1];
__device__ __align__(16) unsigned short g_rank[E_TRAIN];
__device__ __align__(16) unsigned short g_esrc[E_TRAIN];
__device__ float g_dinv[N_NODES];

// ---- degree + rank (8 edges/thread) -----------------------------------------
__global__ void k_zero() {
    int i = blockIdx.x * blockDim.x + threadIdx.x;
    if (i < N_NODES) g_deg[i] = 0;
}

__global__ void k_count(const int* __restrict__ dst) {
    int t = blockIdx.x * 256 + threadIdx.x;
    if (t < E_TRAIN / 8) {
        int4 d0 = __ldg((const int4*)dst + 2 * t);
        int4 d1 = __ldg((const int4*)dst + 2 * t + 1);
        unsigned r0 = atomicAdd(&g_deg[d0.x], 1);
        unsigned r1 = atomicAdd(&g_deg[d0.y], 1);
        unsigned r2 = atomicAdd(&g_deg[d0.z], 1);
        unsigned r3 = atomicAdd(&g_deg[d0.w], 1);
        unsigned r4 = atomicAdd(&g_deg[d1.x], 1);
        unsigned r5 = atomicAdd(&g_deg[d1.y], 1);
        unsigned r6 = atomicAdd(&g_deg[d1.z], 1);
        unsigned r7 = atomicAdd(&g_deg[d1.w], 1);
        uint4 pk;
        pk.x = r0 | (r1 << 16);
        pk.y = r2 | (r3 << 16);
        pk.z = r4 | (r5 << 16);
        pk.w = r6 | (r7 << 16);
        ((uint4*)g_rank)[t] = pk;
    }
}

// ---- single-block exclusive scan -> rowptr/dinv -----------------------------
#define SCAN_T 1024
#define CHUNK  49     // 1024*49 = 50176 >= 50000

__global__ __launch_bounds__(SCAN_T) void k_scan() {
    __shared__ int part[SCAN_T];
    int t = threadIdx.x;
    int base = t * CHUNK;
    int s = 0;
#pragma unroll 7
    for (int i = 0; i < CHUNK; i++) {
        int idx = base + i;
        if (idx < N_NODES) s += __ldg(g_deg + idx);
    }
    part[t] = s;
    __syncthreads();
    for (int off = 1; off < SCAN_T; off <<= 1) {
        int v = (t >= off) ? part[t - off] : 0;
        __syncthreads();
        part[t] += v;
        __syncthreads();
    }
    int run = (t > 0) ? part[t - 1] : 0;
    for (int i = 0; i < CHUNK; i++) {
        int idx = base + i;
        if (idx < N_NODES) {
            int d = g_deg[idx];
            g_rowptr[idx] = run;
            g_dinv[idx]   = rsqrtf((float)(d + 1));   // +1 self loop
            run += d;
        }
    }
    if (t == SCAN_T - 1) g_rowptr[N_NODES] = run;
}

// ---- atomic-free placement (4 edges/thread, TLP over ILP) -------------------
__global__ void k_place(const int* __restrict__ src, const int* __restrict__ dst) {
    int t = blockIdx.x * 256 + threadIdx.x;
    if (t < E_TRAIN / 4) {
        int4 s0 = __ldg((const int4*)src + t);
        int4 d0 = __ldg((const int4*)dst + t);
        uint2 pk = __ldg((const uint2*)g_rank + t);
        int p0 = __ldg(g_rowptr + d0.x) + (pk.x & 0xffff);
        int p1 = __ldg(g_rowptr + d0.y) + (pk.x >> 16);
        int p2 = __ldg(g_rowptr + d0.z) + (pk.y & 0xffff);
        int p3 = __ldg(g_rowptr + d0.w) + (pk.y >> 16);
        g_esrc[p0] = (unsigned short)s0.x;
        g_esrc[p1] = (unsigned short)s0.y;
        g_esrc[p2] = (unsigned short)s0.z;
        g_esrc[p3] = (unsigned short)s0.w;
    }
}

// ---- GEMM 1: bufA = fp16( dinv[i] * (x @ W1) ), W padded to 64 cols --------
__global__ __launch_bounds__(256) void k_gemm1(const float* __restrict__ x,
                                               const float* __restrict__ W1) {
    __shared__ float ws[F_IN][64];
    __shared__ float xs[16][F_IN + 2];
    int tid = threadIdx.x;
    int nodeBase = blockIdx.x * 16;                 // 3125 blocks, always full
    for (int t = tid; t < F_IN * 64; t += 256) {
        int k = t >> 6, j = t & 63;
        ws[k][j] = (j < HID) ? W1[k * HID + j] : 0.f;
    }
    for (int t = tid; t < 16 * F_IN; t += 256) {
        int n = t / F_IN, k = t % F_IN;
        xs[n][k] = x[(nodeBase + n) * F_IN + k];
    }
    __syncthreads();
    int n = tid >> 4, jq = tid & 15;
    int node = nodeBase + n;
    float4 acc = make_float4(0.f, 0.f, 0.f, 0.f);
#pragma unroll
    for (int k = 0; k < F_IN; k++) {
        float xv = xs[n][k];
        float4 w = *(const float4*)&ws[k][jq * 4];
        acc.x = fmaf(xv, w.x, acc.x);
        acc.y = fmaf(xv, w.y, acc.y);
        acc.z = fmaf(xv, w.z, acc.z);
        acc.w = fmaf(xv, w.w, acc.w);
    }
    float di = g_dinv[node];
    __half2 p0 = __floats2half2_rn(acc.x * di, acc.y * di);
    __half2 p1 = __floats2half2_rn(acc.z * di, acc.w * di);
    uint2 st;
    st.x = *(unsigned*)&p0;
    st.y = *(unsigned*)&p1;
    *(uint2*)&g_bufA[node * PAD + jq * 4] = st;
}

// ---- GEMM 2: bufA = fp16( dinv[i] * (bufC @ W2) ) ---------------------------
__global__ __launch_bounds__(256) void k_gemm2(const float* __restrict__ W2) {
    __shared__ float ws[HID][64];
    __shared__ float xs[16][HID + 2];
    int tid = threadIdx.x;
    int nodeBase = blockIdx.x * 16;
    for (int t = tid; t < HID * 64; t += 256) {
        int k = t >> 6, j = t & 63;
        ws[k][j] = W2[k * DOUT + j];
    }
    for (int t = tid; t < 16 * HID; t += 256) {
        int n = t / HID, k = t % HID;
        xs[n][k] = g_bufC[(nodeBase + n) * PAD + k];
    }
    __syncthreads();
    int n = tid >> 4, jq = tid & 15;
    int node = nodeBase + n;
    float4 acc = make_float4(0.f, 0.f, 0.f, 0.f);
#pragma unroll
    for (int k = 0; k < HID; k++) {
        float xv = xs[n][k];
        float4 w = *(const float4*)&ws[k][jq * 4];
        acc.x = fmaf(xv, w.x, acc.x);
        acc.y = fmaf(xv, w.y, acc.y);
        acc.z = fmaf(xv, w.z, acc.z);
        acc.w = fmaf(xv, w.w, acc.w);
    }
    float di = g_dinv[node];
    __half2 p0 = __floats2half2_rn(acc.x * di, acc.y * di);
    __half2 p1 = __floats2half2_rn(acc.z * di, acc.w * di);
    uint2 st;
    st.x = *(unsigned*)&p0;
    st.y = *(unsigned*)&p1;
    *(uint2*)&g_bufA[node * PAD + jq * 4] = st;
}

// ---- CSR aggregation + fused epilogue ---------------------------------------
// One warp per node. 4 edge-groups of 8 lanes; lane q owns 16B chunk q
// (8 halves). CH = active chunks (7 for layer 1).
// FINAL=false: fp32 store to g_bufC (+relu). FINAL=true: fp16 store to g_z.
template <int CH, int NB, bool RELU, bool FINAL>
__global__ __launch_bounds__(256) void k_agg(const float* __restrict__ bias) {
    int node = (blockIdx.x * 256 + threadIdx.x) >> 5;   // 6250 blocks exact
    int lane = threadIdx.x & 31;
    int g = lane >> 3, q = lane & 7;
    int rp = g_rowptr[node], re = g_rowptr[node + 1];
    float a0 = 0.f, a1 = 0.f, a2 = 0.f, a3 = 0.f;
    float a4 = 0.f, a5 = 0.f, a6 = 0.f, a7 = 0.f;
    const uint4* rows = (const uint4*)g_bufA;           // 8 uint4 per row
    const bool act = (CH == 8) || (q < CH);

#define ACCUM(U) do {                                                   \
        __half2* hp = (__half2*)&(U);                                   \
        float2 f0 = __half22float2(hp[0]);                              \
        float2 f1 = __half22float2(hp[1]);                              \
        float2 f2 = __half22float2(hp[2]);                              \
        float2 f3 = __half22float2(hp[3]);                              \
        a0 += f0.x; a1 += f0.y; a2 += f1.x; a3 += f1.y;                 \
        a4 += f2.x; a5 += f2.y; a6 += f3.x; a7 += f3.y;                 \
    } while (0)

    if (g == 0 && act) {                                // self loop
        uint4 u = __ldg(rows + node * 8 + q);
        ACCUM(u);
    }
    int e = rp + g;
    for (; e + 12 < re; e += 16) {
        int s0 = (int)__ldg(g_esrc + e);
        int s1 = (int)__ldg(g_esrc + e + 4);
        int s2 = (int)__ldg(g_esrc + e + 8);
        int s3 = (int)__ldg(g_esrc + e + 12);
        if (act) {
            uint4 u0 = __ldg(rows + s0 * 8 + q);
            uint4 u1 = __ldg(rows + s1 * 8 + q);
            uint4 u2 = __ldg(rows + s2 * 8 + q);
            uint4 u3 = __ldg(rows + s3 * 8 + q);
            ACCUM(u0); ACCUM(u1); ACCUM(u2); ACCUM(u3);
        }
    }
    for (; e + 4 < re; e += 8) {
        int s0 = (int)__ldg(g_esrc + e);
        int s1 = (int)__ldg(g_esrc + e + 4);
        if (act) {
            uint4 u0 = __ldg(rows + s0 * 8 + q);
            uint4 u1 = __ldg(rows + s1 * 8 + q);
            ACCUM(u0); ACCUM(u1);
        }
    }
    if (e < re) {
        int s0 = (int)__ldg(g_esrc + e);
        if (act) {
            uint4 u0 = __ldg(rows + s0 * 8 + q);
            ACCUM(u0);
        }
    }
#undef ACCUM

#define RED(off) do {                                                   \
        a0 += __shfl_xor_sync(0xffffffffu, a0, off);                    \
        a1 += __shfl_xor_sync(0xffffffffu, a1, off);                    \
        a2 += __shfl_xor_sync(0xffffffffu, a2, off);                    \
        a3 += __shfl_xor_sync(0xffffffffu, a3, off);                    \
        a4 += __shfl_xor_sync(0xffffffffu, a4, off);                    \
        a5 += __shfl_xor_sync(0xffffffffu, a5, off);                    \
        a6 += __shfl_xor_sync(0xffffffffu, a6, off);                    \
        a7 += __shfl_xor_sync(0xffffffffu, a7, off);                    \
    } while (0)
    RED(8);
    RED(16);
#undef RED

    if (g == 0 && act) {
        float di = g_dinv[node];
        int j0 = q * 8;
        float acc[8] = {a0, a1, a2, a3, a4, a5, a6, a7};
        float v[8];
#pragma unroll
        for (int i = 0; i < 8; i++) {
            int j = j0 + i;
            float bv = (j < NB) ? __ldg(bias + j) : 0.f;
            float r = fmaf(di, acc[i], bv);
            if (RELU) r = fmaxf(r, 0.f);
            v[i] = r;
        }
        if (FINAL) {
            __half2 h0 = __floats2half2_rn(v[0], v[1]);
            __half2 h1 = __floats2half2_rn(v[2], v[3]);
            __half2 h2 = __floats2half2_rn(v[4], v[5]);
            __half2 h3 = __floats2half2_rn(v[6], v[7]);
            uint4 st;
            st.x = *(unsigned*)&h0; st.y = *(unsigned*)&h1;
            st.z = *(unsigned*)&h2; st.w = *(unsigned*)&h3;
            *(uint4*)&g_z[node * PAD + j0] = st;
        } else {
            float4 r0 = make_float4(v[0], v[1], v[2], v[3]);
            float4 r1 = make_float4(v[4], v[5], v[6], v[7]);
            *(float4*)(g_bufC + node * PAD + j0)     = r0;
            *(float4*)(g_bufC + node * PAD + j0 + 4) = r1;
        }
    }
}

// ---- decode: logits[e] = dot64(z[a], z[b]), z fp16 --------------------------
__global__ void k_decode(const int* __restrict__ pos,
                         const int* __restrict__ neg,
                         float* __restrict__ out) {
    int gt = blockIdx.x * 256 + threadIdx.x;   // 12500 blocks exact
    int e = gt >> 3;
    int j = gt & 7;
    int a, b;
    if (e < EP) { a = pos[e];        b = pos[EP + e]; }
    else        { int e2 = e - EP;  a = neg[e2];     b = neg[EN + e2]; }
    uint4 ua = __ldg((const uint4*)(g_z + a * PAD) + j);
    uint4 ub = __ldg((const uint4*)(g_z + b * PAD) + j);
    __half2* ha = (__half2*)&ua;
    __half2* hb = (__half2*)&ub;
    float s = 0.f;
#pragma unroll
    for (int i = 0; i < 4; i++) {
        float2 fa = __half22float2(ha[i]);
        float2 fb = __half22float2(hb[i]);
        s = fmaf(fa.x, fb.x, s);
        s = fmaf(fa.y, fb.y, s);
    }
#pragma unroll
    for (int o = 4; o; o >>= 1) s += __shfl_xor_sync(0xffffffffu, s, o);
    if (j == 0) out[e] = s;
}

// ---------------------------------------------------------------------------
extern "C" void kernel_launch(void* const* d_in, const int* in_sizes, int n_in,
                              void* d_out, int out_size) {
    const float* x   = (const float*)d_in[0];
    const int*   tr  = (const int*)d_in[1];
    const int*   pos = (const int*)d_in[2];
    const int*   neg = (const int*)d_in[3];
    const float* W1  = (const float*)d_in[4];
    const float* b1  = (const float*)d_in[5];
    const float* W2  = (const float*)d_in[6];
    const float* b2  = (const float*)d_in[7];
    float* out = (float*)d_out;

    const int* src = tr;
    const int* dst = tr + E_TRAIN;

    // Lazy one-time stream/event creation (not device memory; idempotent).
    static cudaStream_t sB = nullptr;
    static cudaEvent_t  evScan = nullptr, evG1 = nullptr;
    if (sB == nullptr) {
        cudaStreamCreateWithFlags(&sB, cudaStreamNonBlocking);
        cudaEventCreateWithFlags(&evScan, cudaEventDisableTiming);
        cudaEventCreateWithFlags(&evG1,   cudaEventDisableTiming);
    }

    // CSR build prefix (default stream)
    k_zero<<<(N_NODES + 255) / 256, 256>>>();
    k_count<<<(E_TRAIN / 8 + 255) / 256, 256>>>(dst);
    k_scan<<<1, SCAN_T>>>();

    // Fork: gemm1 on stream B (needs only dinv from scan) || place (default)
    cudaEventRecord(evScan, 0);
    cudaStreamWaitEvent(sB, evScan, 0);
    k_gemm1<<<N_NODES / 16, 256, 0, sB>>>(x, W1);
    cudaEventRecord(evG1, sB);

    k_place<<<(E_TRAIN / 4 + 255) / 256, 256>>>(src, dst);

    // Join before agg1
    cudaStreamWaitEvent(0, evG1, 0);
    k_agg<7, HID, true, false><<<N_NODES * 32 / 256, 256>>>(b1);

    // layer 2
    k_gemm2<<<N_NODES / 16, 256>>>(W2);
    k_agg<8, DOUT, false, true><<<N_NODES * 32 / 256, 256>>>(b2);

    // decode
    k_decode<<<(EP + EN) * 8 / 256, 256>>>(pos, neg, out);
}

// round 9
// speedup vs baseline: 1.0467x; 1.0150x over previous
#include <cuda_runtime.h>
#include <cuda_fp16.h>

// ---------------------------------------------------------------------------
// GCN link prediction, CSR-gather formulation:
//   h = x@W (fp16, UNSCALED) -> acc[c] = dinv[c]*h[c] + sum dinv[src]*h[src]
//   out[c] = dinv[c]*acc[c] + b  (relu layer 1 -> fp32; layer 2 -> fp16 z)
// dinv applied per-edge inside agg, so the GEMMs have no dependency on the
// degree pass: gemm1 runs on stream B concurrent with the whole CSR build.
// ---------------------------------------------------------------------------

#define N_NODES 50000
#define E_TRAIN 1600000
#define EP      200000
#define EN      200000
#define F_IN    50
#define HID     50
#define DOUT    64
#define PAD     64

__device__ __align__(256) __half g_bufA[N_NODES * PAD]; // h fp16 (gather src)
__device__ __align__(256) float  g_bufC[N_NODES * PAD]; // layer-1 output (fp32)
__device__ __align__(256) __half g_z[N_NODES * PAD];    // layer-2 output (fp16)
__device__ int   g_deg[N_NODES];
__device__ int   g_rowptr[N_NODES + 1];
__device__ __align__(16) unsigned short g_rank[E_TRAIN];
__device__ __align__(16) unsigned short g_esrc[E_TRAIN];
__device__ float g_dinv[N_NODES];

// ---- degree + rank ----------------------------------------------------------
__global__ void k_zero() {
    int i = blockIdx.x * blockDim.x + threadIdx.x;
    if (i < N_NODES) g_deg[i] = 0;
}

__global__ void k_count(const int* __restrict__ dst) {
    int t = blockIdx.x * 256 + threadIdx.x;
    if (t < E_TRAIN / 8) {
        int4 d0 = __ldg((const int4*)dst + 2 * t);
        int4 d1 = __ldg((const int4*)dst + 2 * t + 1);
        unsigned r0 = atomicAdd(&g_deg[d0.x], 1);
        unsigned r1 = atomicAdd(&g_deg[d0.y], 1);
        unsigned r2 = atomicAdd(&g_deg[d0.z], 1);
        unsigned r3 = atomicAdd(&g_deg[d0.w], 1);
        unsigned r4 = atomicAdd(&g_deg[d1.x], 1);
        unsigned r5 = atomicAdd(&g_deg[d1.y], 1);
        unsigned r6 = atomicAdd(&g_deg[d1.z], 1);
        unsigned r7 = atomicAdd(&g_deg[d1.w], 1);
        uint4 pk;
        pk.x = r0 | (r1 << 16);
        pk.y = r2 | (r3 << 16);
        pk.z = r4 | (r5 << 16);
        pk.w = r6 | (r7 << 16);
        ((uint4*)g_rank)[t] = pk;
    }
}

// ---- single-block exclusive scan -> rowptr/dinv -----------------------------
#define SCAN_T 1024
#define CHUNK  49     // 1024*49 = 50176 >= 50000

__global__ __launch_bounds__(SCAN_T) void k_scan() {
    __shared__ int part[SCAN_T];
    int t = threadIdx.x;
    int base = t * CHUNK;
    int s = 0;
#pragma unroll 7
    for (int i = 0; i < CHUNK; i++) {
        int idx = base + i;
        if (idx < N_NODES) s += __ldg(g_deg + idx);
    }
    part[t] = s;
    __syncthreads();
    for (int off = 1; off < SCAN_T; off <<= 1) {
        int v = (t >= off) ? part[t - off] : 0;
        __syncthreads();
        part[t] += v;
        __syncthreads();
    }
    int run = (t > 0) ? part[t - 1] : 0;
    for (int i = 0; i < CHUNK; i++) {
        int idx = base + i;
        if (idx < N_NODES) {
            int d = g_deg[idx];
            g_rowptr[idx] = run;
            g_dinv[idx]   = rsqrtf((float)(d + 1));   // +1 self loop
            run += d;
        }
    }
    if (t == SCAN_T - 1) g_rowptr[N_NODES] = run;
}

// ---- atomic-free placement (4 edges/thread) ---------------------------------
__global__ void k_place(const int* __restrict__ src, const int* __restrict__ dst) {
    int t = blockIdx.x * 256 + threadIdx.x;
    if (t < E_TRAIN / 4) {
        int4 s0 = __ldg((const int4*)src + t);
        int4 d0 = __ldg((const int4*)dst + t);
        uint2 pk = __ldg((const uint2*)g_rank + t);
        int p0 = __ldg(g_rowptr + d0.x) + (pk.x & 0xffff);
        int p1 = __ldg(g_rowptr + d0.y) + (pk.x >> 16);
        int p2 = __ldg(g_rowptr + d0.z) + (pk.y & 0xffff);
        int p3 = __ldg(g_rowptr + d0.w) + (pk.y >> 16);
        g_esrc[p0] = (unsigned short)s0.x;
        g_esrc[p1] = (unsigned short)s0.y;
        g_esrc[p2] = (unsigned short)s0.z;
        g_esrc[p3] = (unsigned short)s0.w;
    }
}

// ---- GEMM 1: bufA = fp16(x @ W1), 32 nodes/block, 2 nodes/thread -----------
__global__ __launch_bounds__(256) void k_gemm1(const float* __restrict__ x,
                                               const float* __restrict__ W1) {
    __shared__ float ws[F_IN][64];
    __shared__ float xs[32][F_IN + 2];
    int tid = threadIdx.x;
    int nodeBase = blockIdx.x * 32;                 // 1563 blocks (last partial)
    for (int t = tid; t < F_IN * 64; t += 256) {
        int k = t >> 6, j = t & 63;
        ws[k][j] = (j < HID) ? W1[k * HID + j] : 0.f;
    }
    for (int t = tid; t < 32 * F_IN; t += 256) {
        int n = t / F_IN, k = t % F_IN;
        int node = nodeBase + n;
        xs[n][k] = (node < N_NODES) ? x[node * F_IN + k] : 0.f;
    }
    __syncthreads();
    int n = tid >> 4, jq = tid & 15;
    int node0 = nodeBase + n;
    int node1 = nodeBase + n + 16;
    float4 accA = make_float4(0.f, 0.f, 0.f, 0.f);
    float4 accB = make_float4(0.f, 0.f, 0.f, 0.f);
#pragma unroll
    for (int k = 0; k < F_IN; k++) {
        float4 w = *(const float4*)&ws[k][jq * 4];
        float xv0 = xs[n][k];
        float xv1 = xs[n + 16][k];
        accA.x = fmaf(xv0, w.x, accA.x);
        accA.y = fmaf(xv0, w.y, accA.y);
        accA.z = fmaf(xv0, w.z, accA.z);
        accA.w = fmaf(xv0, w.w, accA.w);
        accB.x = fmaf(xv1, w.x, accB.x);
        accB.y = fmaf(xv1, w.y, accB.y);
        accB.z = fmaf(xv1, w.z, accB.z);
        accB.w = fmaf(xv1, w.w, accB.w);
    }
    if (node0 < N_NODES) {
        __half2 p0 = __floats2half2_rn(accA.x, accA.y);
        __half2 p1 = __floats2half2_rn(accA.z, accA.w);
        uint2 st; st.x = *(unsigned*)&p0; st.y = *(unsigned*)&p1;
        *(uint2*)&g_bufA[node0 * PAD + jq * 4] = st;
    }
    if (node1 < N_NODES) {
        __half2 p0 = __floats2half2_rn(accB.x, accB.y);
        __half2 p1 = __floats2half2_rn(accB.z, accB.w);
        uint2 st; st.x = *(unsigned*)&p0; st.y = *(unsigned*)&p1;
        *(uint2*)&g_bufA[node1 * PAD + jq * 4] = st;
    }
}

// ---- GEMM 2: bufA = fp16(bufC @ W2), 32 nodes/block -------------------------
__global__ __launch_bounds__(256) void k_gemm2(const float* __restrict__ W2) {
    __shared__ float ws[HID][64];
    __shared__ float xs[32][HID + 2];
    int tid = threadIdx.x;
    int nodeBase = blockIdx.x * 32;
    for (int t = tid; t < HID * 64; t += 256) {
        int k = t >> 6, j = t & 63;
        ws[k][j] = W2[k * DOUT + j];
    }
    for (int t = tid; t < 32 * HID; t += 256) {
        int n = t / HID, k = t % HID;
        int node = nodeBase + n;
        xs[n][k] = (node < N_NODES) ? g_bufC[node * PAD + k] : 0.f;
    }
    __syncthreads();
    int n = tid >> 4, jq = tid & 15;
    int node0 = nodeBase + n;
    int node1 = nodeBase + n + 16;
    float4 accA = make_float4(0.f, 0.f, 0.f, 0.f);
    float4 accB = make_float4(0.f, 0.f, 0.f, 0.f);
#pragma unroll
    for (int k = 0; k < HID; k++) {
        float4 w = *(const float4*)&ws[k][jq * 4];
        float xv0 = xs[n][k];
        float xv1 = xs[n + 16][k];
        accA.x = fmaf(xv0, w.x, accA.x);
        accA.y = fmaf(xv0, w.y, accA.y);
        accA.z = fmaf(xv0, w.z, accA.z);
        accA.w = fmaf(xv0, w.w, accA.w);
        accB.x = fmaf(xv1, w.x, accB.x);
        accB.y = fmaf(xv1, w.y, accB.y);
        accB.z = fmaf(xv1, w.z, accB.z);
        accB.w = fmaf(xv1, w.w, accB.w);
    }
    if (node0 < N_NODES) {
        __half2 p0 = __floats2half2_rn(accA.x, accA.y);
        __half2 p1 = __floats2half2_rn(accA.z, accA.w);
        uint2 st; st.x = *(unsigned*)&p0; st.y = *(unsigned*)&p1;
        *(uint2*)&g_bufA[node0 * PAD + jq * 4] = st;
    }
    if (node1 < N_NODES) {
        __half2 p0 = __floats2half2_rn(accB.x, accB.y);
        __half2 p1 = __floats2half2_rn(accB.z, accB.w);
        uint2 st; st.x = *(unsigned*)&p0; st.y = *(unsigned*)&p1;
        *(uint2*)&g_bufA[node1 * PAD + jq * 4] = st;
    }
}

// ---- CSR aggregation + fused epilogue ---------------------------------------
// One warp per node. 4 edge-groups of 8 lanes; lane q owns 16B chunk q.
// Rows are UNSCALED h; each edge contributes dinv[src]*h[src] (dinv via
// 8-lane broadcast load). CH = active chunks (7 for layer 1).
template <int CH, int NB, bool RELU, bool FINAL>
__global__ __launch_bounds__(256) void k_agg(const float* __restrict__ bias) {
    int node = (blockIdx.x * 256 + threadIdx.x) >> 5;   // 6250 blocks exact
    int lane = threadIdx.x & 31;
    int g = lane >> 3, q = lane & 7;
    int rp = g_rowptr[node], re = g_rowptr[node + 1];
    float a0 = 0.f, a1 = 0.f, a2 = 0.f, a3 = 0.f;
    float a4 = 0.f, a5 = 0.f, a6 = 0.f, a7 = 0.f;
    const uint4* rows = (const uint4*)g_bufA;           // 8 uint4 per row
    const bool act = (CH == 8) || (q < CH);

#define ACCUM(U, D) do {                                                \
        __half2* hp = (__half2*)&(U);                                   \
        float2 f0 = __half22float2(hp[0]);                              \
        float2 f1 = __half22float2(hp[1]);                              \
        float2 f2 = __half22float2(hp[2]);                              \
        float2 f3 = __half22float2(hp[3]);                              \
        a0 = fmaf((D), f0.x, a0); a1 = fmaf((D), f0.y, a1);             \
        a2 = fmaf((D), f1.x, a2); a3 = fmaf((D), f1.y, a3);             \
        a4 = fmaf((D), f2.x, a4); a5 = fmaf((D), f2.y, a5);             \
        a6 = fmaf((D), f3.x, a6); a7 = fmaf((D), f3.y, a7);             \
    } while (0)

    if (g == 0 && act) {                                // self loop
        uint4 u = __ldg(rows + node * 8 + q);
        float d = __ldg(g_dinv + node);
        ACCUM(u, d);
    }
    int e = rp + g;
    for (; e + 12 < re; e += 16) {
        int s0 = (int)__ldg(g_esrc + e);
        int s1 = (int)__ldg(g_esrc + e + 4);
        int s2 = (int)__ldg(g_esrc + e + 8);
        int s3 = (int)__ldg(g_esrc + e + 12);
        if (act) {
            float d0 = __ldg(g_dinv + s0);
            float d1 = __ldg(g_dinv + s1);
            float d2 = __ldg(g_dinv + s2);
            float d3 = __ldg(g_dinv + s3);
            uint4 u0 = __ldg(rows + s0 * 8 + q);
            uint4 u1 = __ldg(rows + s1 * 8 + q);
            uint4 u2 = __ldg(rows + s2 * 8 + q);
            uint4 u3 = __ldg(rows + s3 * 8 + q);
            ACCUM(u0, d0); ACCUM(u1, d1); ACCUM(u2, d2); ACCUM(u3, d3);
        }
    }
    for (; e + 4 < re; e += 8) {
        int s0 = (int)__ldg(g_esrc + e);
        int s1 = (int)__ldg(g_esrc + e + 4);
        if (act) {
            float d0 = __ldg(g_dinv + s0);
            float d1 = __ldg(g_dinv + s1);
            uint4 u0 = __ldg(rows + s0 * 8 + q);
            uint4 u1 = __ldg(rows + s1 * 8 + q);
            ACCUM(u0, d0); ACCUM(u1, d1);
        }
    }
    if (e < re) {
        int s0 = (int)__ldg(g_esrc + e);
        if (act) {
            float d0 = __ldg(g_dinv + s0);
            uint4 u0 = __ldg(rows + s0 * 8 + q);
            ACCUM(u0, d0);
        }
    }
#undef ACCUM

#define RED(off) do {                                                   \
        a0 += __shfl_xor_sync(0xffffffffu, a0, off);                    \
        a1 += __shfl_xor_sync(0xffffffffu, a1, off);                    \
        a2 += __shfl_xor_sync(0xffffffffu, a2, off);                    \
        a3 += __shfl_xor_sync(0xffffffffu, a3, off);                    \
        a4 += __shfl_xor_sync(0xffffffffu, a4, off);                    \
        a5 += __shfl_xor_sync(0xffffffffu, a5, off);                    \
        a6 += __shfl_xor_sync(0xffffffffu, a6, off);                    \
        a7 += __shfl_xor_sync(0xffffffffu, a7, off);                    \
    } while (0)
    RED(8);
    RED(16);
#undef RED

    if (g == 0 && act) {
        float di = g_dinv[node];
        int j0 = q * 8;
        float acc[8] = {a0, a1, a2, a3, a4, a5, a6, a7};
        float v[8];
#pragma unroll
        for (int i = 0; i < 8; i++) {
            int j = j0 + i;
            float bv = (j < NB) ? __ldg(bias + j) : 0.f;
            float r = fmaf(di, acc[i], bv);
            if (RELU) r = fmaxf(r, 0.f);
            v[i] = r;
        }
        if (FINAL) {
            __half2 h0 = __floats2half2_rn(v[0], v[1]);
            __half2 h1 = __floats2half2_rn(v[2], v[3]);
            __half2 h2 = __floats2half2_rn(v[4], v[5]);
            __half2 h3 = __floats2half2_rn(v[6], v[7]);
            uint4 st;
            st.x = *(unsigned*)&h0; st.y = *(unsigned*)&h1;
            st.z = *(unsigned*)&h2; st.w = *(unsigned*)&h3;
            *(uint4*)&g_z[node * PAD + j0] = st;
        } else {
            float4 r0 = make_float4(v[0], v[1], v[2], v[3]);
            float4 r1 = make_float4(v[4], v[5], v[6], v[7]);
            *(float4*)(g_bufC + node * PAD + j0)     = r0;
            *(float4*)(g_bufC + node * PAD + j0 + 4) = r1;
        }
    }
}

// ---- decode: logits[e] = dot64(z[a], z[b]), z fp16 --------------------------
__global__ void k_decode(const int* __restrict__ pos,
                         const int* __restrict__ neg,
                         float* __restrict__ out) {
    int gt = blockIdx.x * 256 + threadIdx.x;   // 12500 blocks exact
    int e = gt >> 3;
    int j = gt & 7;
    int a, b;
    if (e < EP) { a = pos[e];        b = pos[EP + e]; }
    else        { int e2 = e - EP;  a = neg[e2];     b = neg[EN + e2]; }
    uint4 ua = __ldg((const uint4*)(g_z + a * PAD) + j);
    uint4 ub = __ldg((const uint4*)(g_z + b * PAD) + j);
    __half2* ha = (__half2*)&ua;
    __half2* hb = (__half2*)&ub;
    float s = 0.f;
#pragma unroll
    for (int i = 0; i < 4; i++) {
        float2 fa = __half22float2(ha[i]);
        float2 fb = __half22float2(hb[i]);
        s = fmaf(fa.x, fb.x, s);
        s = fmaf(fa.y, fb.y, s);
    }
#pragma unroll
    for (int o = 4; o; o >>= 1) s += __shfl_xor_sync(0xffffffffu, s, o);
    if (j == 0) out[e] = s;
}

// ---------------------------------------------------------------------------
extern "C" void kernel_launch(void* const* d_in, const int* in_sizes, int n_in,
                              void* d_out, int out_size) {
    const float* x   = (const float*)d_in[0];
    const int*   tr  = (const int*)d_in[1];
    const int*   pos = (const int*)d_in[2];
    const int*   neg = (const int*)d_in[3];
    const float* W1  = (const float*)d_in[4];
    const float* b1  = (const float*)d_in[5];
    const float* W2  = (const float*)d_in[6];
    const float* b2  = (const float*)d_in[7];
    float* out = (float*)d_out;

    const int* src = tr;
    const int* dst = tr + E_TRAIN;

    static cudaStream_t sB = nullptr;
    static cudaEvent_t  evStart = nullptr, evG1 = nullptr;
    if (sB == nullptr) {
        cudaStreamCreateWithFlags(&sB, cudaStreamNonBlocking);
        cudaEventCreateWithFlags(&evStart, cudaEventDisableTiming);
        cudaEventCreateWithFlags(&evG1,    cudaEventDisableTiming);
    }

    // Fork at t=0: gemm1 (no dependency on the build) on stream B.
    cudaEventRecord(evStart, 0);
    cudaStreamWaitEvent(sB, evStart, 0);
    k_gemm1<<<(N_NODES + 31) / 32, 256, 0, sB>>>(x, W1);
    cudaEventRecord(evG1, sB);

    // CSR build on default stream, concurrent with gemm1.
    k_zero<<<(N_NODES + 255) / 256, 256>>>();
    k_count<<<(E_TRAIN / 8 + 255) / 256, 256>>>(dst);
    k_scan<<<1, SCAN_T>>>();
    k_place<<<(E_TRAIN / 4 + 255) / 256, 256>>>(src, dst);

    // Join, then layer 1 aggregation.
    cudaStreamWaitEvent(0, evG1, 0);
    k_agg<7, HID, true, false><<<N_NODES * 32 / 256, 256>>>(b1);

    // layer 2
    k_gemm2<<<(N_NODES + 31) / 32, 256>>>(W2);
    k_agg<8, DOUT, false, true><<<N_NODES * 32 / 256, 256>>>(b2);

    // decode
    k_decode<<<(EP + EN) * 8 / 256, 256>>>(pos, neg, out);
}

// round 12
// speedup vs baseline: 1.5042x; 1.4371x over previous
#include <cuda_runtime.h>
#include <cuda_fp16.h>

// ---------------------------------------------------------------------------
// GCN link prediction, CSR-gather formulation:
//   h = x@W (fp16, UNSCALED) -> acc[c] = dinv[c]*h[c] + sum dinv[src]*h[src]
//   out[c] = dinv[c]*acc[c] + b  (relu layer 1 -> fp32; layer 2 -> fp16 z)
// dinv applied per-edge inside agg => gemm1 has no dependency on the CSR
// build and runs on stream B concurrent with it.
// Round 9 fix: single-block 78us scan replaced by 3-phase multi-block scan.
// ---------------------------------------------------------------------------

#define N_NODES 50000
#define E_TRAIN 1600000
#define EP      200000
#define EN      200000
#define F_IN    50
#define HID     50
#define DOUT    64
#define PAD     64

#define SCAN_B  1024
#define SCAN_NBLK ((N_NODES + SCAN_B - 1) / SCAN_B)   // 49

__device__ __align__(256) __half g_bufA[N_NODES * PAD]; // h fp16 (gather src)
__device__ __align__(256) float  g_bufC[N_NODES * PAD]; // layer-1 output (fp32)
__device__ __align__(256) __half g_z[N_NODES * PAD];    // layer-2 output (fp16)
__device__ int   g_deg[N_NODES];
__device__ int   g_rowptr[N_NODES + 1];
__device__ int   g_bsum[SCAN_NBLK];
__device__ int   g_boff[SCAN_NBLK];
__device__ __align__(16) unsigned short g_rank[E_TRAIN];
__device__ __align__(16) unsigned short g_esrc[E_TRAIN];
__device__ float g_dinv[N_NODES];

// ---- degree + rank ----------------------------------------------------------
__global__ void k_zero() {
    int i = blockIdx.x * blockDim.x + threadIdx.x;
    if (i < N_NODES) g_deg[i] = 0;
}

__global__ void k_count(const int* __restrict__ dst) {
    int t = blockIdx.x * 256 + threadIdx.x;
    if (t < E_TRAIN / 8) {
        int4 d0 = __ldg((const int4*)dst + 2 * t);
        int4 d1 = __ldg((const int4*)dst + 2 * t + 1);
        unsigned r0 = atomicAdd(&g_deg[d0.x], 1);
        unsigned r1 = atomicAdd(&g_deg[d0.y], 1);
        unsigned r2 = atomicAdd(&g_deg[d0.z], 1);
        unsigned r3 = atomicAdd(&g_deg[d0.w], 1);
        unsigned r4 = atomicAdd(&g_deg[d1.x], 1);
        unsigned r5 = atomicAdd(&g_deg[d1.y], 1);
        unsigned r6 = atomicAdd(&g_deg[d1.z], 1);
        unsigned r7 = atomicAdd(&g_deg[d1.w], 1);
        uint4 pk;
        pk.x = r0 | (r1 << 16);
        pk.y = r2 | (r3 << 16);
        pk.z = r4 | (r5 << 16);
        pk.w = r6 | (r7 << 16);
        ((uint4*)g_rank)[t] = pk;
    }
}

// ---- 3-phase multi-block exclusive scan -> rowptr/dinv ----------------------
// Phase 1: per-block exclusive scan (local) + block sums + dinv.
__global__ __launch_bounds__(SCAN_B) void k_scan_local() {
    __shared__ int sh[SCAN_B];
    int t = threadIdx.x;
    int gid = blockIdx.x * SCAN_B + t;
    int d = (gid < N_NODES) ? g_deg[gid] : 0;
    int val = d;
    sh[t] = val;
    __syncthreads();
    for (int off = 1; off < SCAN_B; off <<= 1) {
        int v = (t >= off) ? sh[t - off] : 0;
        __syncthreads();
        val += v;
        sh[t] = val;
        __syncthreads();
    }
    if (gid < N_NODES) {
        g_rowptr[gid] = val - d;                 // local exclusive prefix
        g_dinv[gid]   = rsqrtf((float)(d + 1));  // +1 self loop
    }
    if (t == SCAN_B - 1) g_bsum[blockIdx.x] = val;
}

// Phase 2: scan the block sums (tiny).
__global__ void k_scan_bsum() {
    __shared__ int sh[SCAN_NBLK];
    int t = threadIdx.x;   // 64 threads
    if (t < SCAN_NBLK) sh[t] = g_bsum[t];
    __syncthreads();
    if (t == 0) {
        int run = 0;
#pragma unroll
        for (int i = 0; i < SCAN_NBLK; i++) {
            int d = sh[i];
            sh[i] = run;
            run += d;
        }
        g_rowptr[N_NODES] = run;
    }
    __syncthreads();
    if (t < SCAN_NBLK) g_boff[t] = sh[t];
}

// Phase 3: add block offsets.
__global__ __launch_bounds__(SCAN_B) void k_scan_add() {
    int gid = blockIdx.x * SCAN_B + threadIdx.x;
    if (gid < N_NODES) g_rowptr[gid] += __ldg(g_boff + blockIdx.x);
}

// ---- atomic-free placement (4 edges/thread) ---------------------------------
__global__ void k_place(const int* __restrict__ src, const int* __restrict__ dst) {
    int t = blockIdx.x * 256 + threadIdx.x;
    if (t < E_TRAIN / 4) {
        int4 s0 = __ldg((const int4*)src + t);
        int4 d0 = __ldg((const int4*)dst + t);
        uint2 pk = __ldg((const uint2*)g_rank + t);
        int p0 = __ldg(g_rowptr + d0.x) + (pk.x & 0xffff);
        int p1 = __ldg(g_rowptr + d0.y) + (pk.x >> 16);
        int p2 = __ldg(g_rowptr + d0.z) + (pk.y & 0xffff);
        int p3 = __ldg(g_rowptr + d0.w) + (pk.y >> 16);
        g_esrc[p0] = (unsigned short)s0.x;
        g_esrc[p1] = (unsigned short)s0.y;
        g_esrc[p2] = (unsigned short)s0.z;
        g_esrc[p3] = (unsigned short)s0.w;
    }
}

// ---- GEMM 1: bufA = fp16(x @ W1), 32 nodes/block, 2 nodes/thread -----------
__global__ __launch_bounds__(256) void k_gemm1(const float* __restrict__ x,
                                               const float* __restrict__ W1) {
    __shared__ float ws[F_IN][64];
    __shared__ float xs[32][F_IN + 2];
    int tid = threadIdx.x;
    int nodeBase = blockIdx.x * 32;                 // 1563 blocks (last partial)
    for (int t = tid; t < F_IN * 64; t += 256) {
        int k = t >> 6, j = t & 63;
        ws[k][j] = (j < HID) ? W1[k * HID + j] : 0.f;
    }
    for (int t = tid; t < 32 * F_IN; t += 256) {
        int n = t / F_IN, k = t % F_IN;
        int node = nodeBase + n;
        xs[n][k] = (node < N_NODES) ? x[node * F_IN + k] : 0.f;
    }
    __syncthreads();
    int n = tid >> 4, jq = tid & 15;
    int node0 = nodeBase + n;
    int node1 = nodeBase + n + 16;
    float4 accA = make_float4(0.f, 0.f, 0.f, 0.f);
    float4 accB = make_float4(0.f, 0.f, 0.f, 0.f);
#pragma unroll
    for (int k = 0; k < F_IN; k++) {
        float4 w = *(const float4*)&ws[k][jq * 4];
        float xv0 = xs[n][k];
        float xv1 = xs[n + 16][k];
        accA.x = fmaf(xv0, w.x, accA.x);
        accA.y = fmaf(xv0, w.y, accA.y);
        accA.z = fmaf(xv0, w.z, accA.z);
        accA.w = fmaf(xv0, w.w, accA.w);
        accB.x = fmaf(xv1, w.x, accB.x);
        accB.y = fmaf(xv1, w.y, accB.y);
        accB.z = fmaf(xv1, w.z, accB.z);
        accB.w = fmaf(xv1, w.w, accB.w);
    }
    if (node0 < N_NODES) {
        __half2 p0 = __floats2half2_rn(accA.x, accA.y);
        __half2 p1 = __floats2half2_rn(accA.z, accA.w);
        uint2 st; st.x = *(unsigned*)&p0; st.y = *(unsigned*)&p1;
        *(uint2*)&g_bufA[node0 * PAD + jq * 4] = st;
    }
    if (node1 < N_NODES) {
        __half2 p0 = __floats2half2_rn(accB.x, accB.y);
        __half2 p1 = __floats2half2_rn(accB.z, accB.w);
        uint2 st; st.x = *(unsigned*)&p0; st.y = *(unsigned*)&p1;
        *(uint2*)&g_bufA[node1 * PAD + jq * 4] = st;
    }
}

// ---- GEMM 2: bufA = fp16(bufC @ W2), 32 nodes/block -------------------------
__global__ __launch_bounds__(256) void k_gemm2(const float* __restrict__ W2) {
    __shared__ float ws[HID][64];
    __shared__ float xs[32][HID + 2];
    int tid = threadIdx.x;
    int nodeBase = blockIdx.x * 32;
    for (int t = tid; t < HID * 64; t += 256) {
        int k = t >> 6, j = t & 63;
        ws[k][j] = W2[k * DOUT + j];
    }
    for (int t = tid; t < 32 * HID; t += 256) {
        int n = t / HID, k = t % HID;
        int node = nodeBase + n;
        xs[n][k] = (node < N_NODES) ? g_bufC[node * PAD + k] : 0.f;
    }
    __syncthreads();
    int n = tid >> 4, jq = tid & 15;
    int node0 = nodeBase + n;
    int node1 = nodeBase + n + 16;
    float4 accA = make_float4(0.f, 0.f, 0.f, 0.f);
    float4 accB = make_float4(0.f, 0.f, 0.f, 0.f);
#pragma unroll
    for (int k = 0; k < HID; k++) {
        float4 w = *(const float4*)&ws[k][jq * 4];
        float xv0 = xs[n][k];
        float xv1 = xs[n + 16][k];
        accA.x = fmaf(xv0, w.x, accA.x);
        accA.y = fmaf(xv0, w.y, accA.y);
        accA.z = fmaf(xv0, w.z, accA.z);
        accA.w = fmaf(xv0, w.w, accA.w);
        accB.x = fmaf(xv1, w.x, accB.x);
        accB.y = fmaf(xv1, w.y, accB.y);
        accB.z = fmaf(xv1, w.z, accB.z);
        accB.w = fmaf(xv1, w.w, accB.w);
    }
    if (node0 < N_NODES) {
        __half2 p0 = __floats2half2_rn(accA.x, accA.y);
        __half2 p1 = __floats2half2_rn(accA.z, accA.w);
        uint2 st; st.x = *(unsigned*)&p0; st.y = *(unsigned*)&p1;
        *(uint2*)&g_bufA[node0 * PAD + jq * 4] = st;
    }
    if (node1 < N_NODES) {
        __half2 p0 = __floats2half2_rn(accB.x, accB.y);
        __half2 p1 = __floats2half2_rn(accB.z, accB.w);
        uint2 st; st.x = *(unsigned*)&p0; st.y = *(unsigned*)&p1;
        *(uint2*)&g_bufA[node1 * PAD + jq * 4] = st;
    }
}

// ---- CSR aggregation + fused epilogue ---------------------------------------
// One warp per node. 4 edge-groups of 8 lanes; lane q owns 16B chunk q.
// Rows are UNSCALED h; each edge contributes dinv[src]*h[src].
template <int CH, int NB, bool RELU, bool FINAL>
__global__ __launch_bounds__(256) void k_agg(const float* __restrict__ bias) {
    int node = (blockIdx.x * 256 + threadIdx.x) >> 5;   // 6250 blocks exact
    int lane = threadIdx.x & 31;
    int g = lane >> 3, q = lane & 7;
    int rp = g_rowptr[node], re = g_rowptr[node + 1];
    float a0 = 0.f, a1 = 0.f, a2 = 0.f, a3 = 0.f;
    float a4 = 0.f, a5 = 0.f, a6 = 0.f, a7 = 0.f;
    const uint4* rows = (const uint4*)g_bufA;           // 8 uint4 per row
    const bool act = (CH == 8) || (q < CH);

#define ACCUM(U, D) do {                                                \
        __half2* hp = (__half2*)&(U);                                   \
        float2 f0 = __half22float2(hp[0]);                              \
        float2 f1 = __half22float2(hp[1]);                              \
        float2 f2 = __half22float2(hp[2]);                              \
        float2 f3 = __half22float2(hp[3]);                              \
        a0 = fmaf((D), f0.x, a0); a1 = fmaf((D), f0.y, a1);             \
        a2 = fmaf((D), f1.x, a2); a3 = fmaf((D), f1.y, a3);             \
        a4 = fmaf((D), f2.x, a4); a5 = fmaf((D), f2.y, a5);             \
        a6 = fmaf((D), f3.x, a6); a7 = fmaf((D), f3.y, a7);             \
    } while (0)

    if (g == 0 && act) {                                // self loop
        uint4 u = __ldg(rows + node * 8 + q);
        float d = __ldg(g_dinv + node);
        ACCUM(u, d);
    }
    int e = rp + g;
    for (; e + 12 < re; e += 16) {
        int s0 = (int)__ldg(g_esrc + e);
        int s1 = (int)__ldg(g_esrc + e + 4);
        int s2 = (int)__ldg(g_esrc + e + 8);
        int s3 = (int)__ldg(g_esrc + e + 12);
        if (act) {
            float d0 = __ldg(g_dinv + s0);
            float d1 = __ldg(g_dinv + s1);
            float d2 = __ldg(g_dinv + s2);
            float d3 = __ldg(g_dinv + s3);
            uint4 u0 = __ldg(rows + s0 * 8 + q);
            uint4 u1 = __ldg(rows + s1 * 8 + q);
            uint4 u2 = __ldg(rows + s2 * 8 + q);
            uint4 u3 = __ldg(rows + s3 * 8 + q);
            ACCUM(u0, d0); ACCUM(u1, d1); ACCUM(u2, d2); ACCUM(u3, d3);
        }
    }
    for (; e + 4 < re; e += 8) {
        int s0 = (int)__ldg(g_esrc + e);
        int s1 = (int)__ldg(g_esrc + e + 4);
        if (act) {
            float d0 = __ldg(g_dinv + s0);
            float d1 = __ldg(g_dinv + s1);
            uint4 u0 = __ldg(rows + s0 * 8 + q);
            uint4 u1 = __ldg(rows + s1 * 8 + q);
            ACCUM(u0, d0); ACCUM(u1, d1);
        }
    }
    if (e < re) {
        int s0 = (int)__ldg(g_esrc + e);
        if (act) {
            float d0 = __ldg(g_dinv + s0);
            uint4 u0 = __ldg(rows + s0 * 8 + q);
            ACCUM(u0, d0);
        }
    }
#undef ACCUM

#define RED(off) do {                                                   \
        a0 += __shfl_xor_sync(0xffffffffu, a0, off);                    \
        a1 += __shfl_xor_sync(0xffffffffu, a1, off);                    \
        a2 += __shfl_xor_sync(0xffffffffu, a2, off);                    \
        a3 += __shfl_xor_sync(0xffffffffu, a3, off);                    \
        a4 += __shfl_xor_sync(0xffffffffu, a4, off);                    \
        a5 += __shfl_xor_sync(0xffffffffu, a5, off);                    \
        a6 += __shfl_xor_sync(0xffffffffu, a6, off);                    \
        a7 += __shfl_xor_sync(0xffffffffu, a7, off);                    \
    } while (0)
    RED(8);
    RED(16);
#undef RED

    if (g == 0 && act) {
        float di = g_dinv[node];
        int j0 = q * 8;
        float acc[8] = {a0, a1, a2, a3, a4, a5, a6, a7};
        float v[8];
#pragma unroll
        for (int i = 0; i < 8; i++) {
            int j = j0 + i;
            float bv = (j < NB) ? __ldg(bias + j) : 0.f;
            float r = fmaf(di, acc[i], bv);
            if (RELU) r = fmaxf(r, 0.f);
            v[i] = r;
        }
        if (FINAL) {
            __half2 h0 = __floats2half2_rn(v[0], v[1]);
            __half2 h1 = __floats2half2_rn(v[2], v[3]);
            __half2 h2 = __floats2half2_rn(v[4], v[5]);
            __half2 h3 = __floats2half2_rn(v[6], v[7]);
            uint4 st;
            st.x = *(unsigned*)&h0; st.y = *(unsigned*)&h1;
            st.z = *(unsigned*)&h2; st.w = *(unsigned*)&h3;
            *(uint4*)&g_z[node * PAD + j0] = st;
        } else {
            float4 r0 = make_float4(v[0], v[1], v[2], v[3]);
            float4 r1 = make_float4(v[4], v[5], v[6], v[7]);
            *(float4*)(g_bufC + node * PAD + j0)     = r0;
            *(float4*)(g_bufC + node * PAD + j0 + 4) = r1;
        }
    }
}

// ---- decode: logits[e] = dot64(z[a], z[b]), z fp16 --------------------------
__global__ void k_decode(const int* __restrict__ pos,
                         const int* __restrict__ neg,
                         float* __restrict__ out) {
    int gt = blockIdx.x * 256 + threadIdx.x;   // 12500 blocks exact
    int e = gt >> 3;
    int j = gt & 7;
    int a, b;
    if (e < EP) { a = pos[e];        b = pos[EP + e]; }
    else        { int e2 = e - EP;  a = neg[e2];     b = neg[EN + e2]; }
    uint4 ua = __ldg((const uint4*)(g_z + a * PAD) + j);
    uint4 ub = __ldg((const uint4*)(g_z + b * PAD) + j);
    __half2* ha = (__half2*)&ua;
    __half2* hb = (__half2*)&ub;
    float s = 0.f;
#pragma unroll
    for (int i = 0; i < 4; i++) {
        float2 fa = __half22float2(ha[i]);
        float2 fb = __half22float2(hb[i]);
        s = fmaf(fa.x, fb.x, s);
        s = fmaf(fa.y, fb.y, s);
    }
#pragma unroll
    for (int o = 4; o; o >>= 1) s += __shfl_xor_sync(0xffffffffu, s, o);
    if (j == 0) out[e] = s;
}

// ---------------------------------------------------------------------------
extern "C" void kernel_launch(void* const* d_in, const int* in_sizes, int n_in,
                              void* d_out, int out_size) {
    const float* x   = (const float*)d_in[0];
    const int*   tr  = (const int*)d_in[1];
    const int*   pos = (const int*)d_in[2];
    const int*   neg = (const int*)d_in[3];
    const float* W1  = (const float*)d_in[4];
    const float* b1  = (const float*)d_in[5];
    const float* W2  = (const float*)d_in[6];
    const float* b2  = (const float*)d_in[7];
    float* out = (float*)d_out;

    const int* src = tr;
    const int* dst = tr + E_TRAIN;

    static cudaStream_t sB = nullptr;
    static cudaEvent_t  evStart = nullptr, evG1 = nullptr;
    if (sB == nullptr) {
        cudaStreamCreateWithFlags(&sB, cudaStreamNonBlocking);
        cudaEventCreateWithFlags(&evStart, cudaEventDisableTiming);
        cudaEventCreateWithFlags(&evG1,    cudaEventDisableTiming);
    }

    // Fork at t=0: gemm1 (no dependency on the build) on stream B.
    cudaEventRecord(evStart, 0);
    cudaStreamWaitEvent(sB, evStart, 0);
    k_gemm1<<<(N_NODES + 31) / 32, 256, 0, sB>>>(x, W1);
    cudaEventRecord(evG1, sB);

    // CSR build on default stream, concurrent with gemm1.
    k_zero<<<(N_NODES + 255) / 256, 256>>>();
    k_count<<<(E_TRAIN / 8 + 255) / 256, 256>>>(dst);
    k_scan_local<<<SCAN_NBLK, SCAN_B>>>();
    k_scan_bsum<<<1, 64>>>();
    k_scan_add<<<SCAN_NBLK, SCAN_B>>>();
    k_place<<<(E_TRAIN / 4 + 255) / 256, 256>>>(src, dst);

    // Join, then layer 1 aggregation.
    cudaStreamWaitEvent(0, evG1, 0);
    k_agg<7, HID, true, false><<<N_NODES * 32 / 256, 256>>>(b1);

    // layer 2
    k_gemm2<<<(N_NODES + 31) / 32, 256>>>(W2);
    k_agg<8, DOUT, false, true><<<N_NODES * 32 / 256, 256>>>(b2);

    // decode
    k_decode<<<(EP + EN) * 8 / 256, 256>>>(pos, neg, out);
}

// round 14
// speedup vs baseline: 1.6648x; 1.1068x over previous
#include <cuda_runtime.h>
#include <cuda_fp16.h>

// ---------------------------------------------------------------------------
// GCN link prediction, CSR-gather formulation:
//   layer: hs = dinv*(x@W) (fp16 rows) ; acc[c] = hs[c] + sum_{dst=c} hs[src]
//          out[c] = dinv[c]*acc[c] + b   (relu layer 1; layer 2 -> fp16 z)
// gemm1 stores UNSCALED h (no scan dependency, runs at t=0 on stream B);
// a tiny k_scale (after gemm1 + scan, concurrent with place) applies dinv.
// gemm2 folds dinv into its store directly. Aggs: 2 loads/edge, no dinv.
// ---------------------------------------------------------------------------

#define N_NODES 50000
#define E_TRAIN 1600000
#define EP      200000
#define EN      200000
#define F_IN    50
#define HID     50
#define DOUT    64
#define PAD     64

#define SCAN_B  1024
#define SCAN_NBLK ((N_NODES + SCAN_B - 1) / SCAN_B)   // 49

__device__ __align__(256) __half g_bufA[N_NODES * PAD]; // hs fp16 (gather src)
__device__ __align__(256) float  g_bufC[N_NODES * PAD]; // layer-1 output (fp32)
__device__ __align__(256) __half g_z[N_NODES * PAD];    // layer-2 output (fp16)
__device__ int   g_deg[N_NODES];
__device__ int   g_rowptr[N_NODES + 1];
__device__ int   g_bsum[SCAN_NBLK];
__device__ int   g_boff[SCAN_NBLK];
__device__ __align__(16) unsigned short g_rank[E_TRAIN];
__device__ __align__(16) unsigned short g_esrc[E_TRAIN];
__device__ float g_dinv[N_NODES];

// ---- degree + rank ----------------------------------------------------------
__global__ void k_zero() {
    int i = blockIdx.x * blockDim.x + threadIdx.x;
    if (i < N_NODES) g_deg[i] = 0;
}

__global__ void k_count(const int* __restrict__ dst) {
    int t = blockIdx.x * 256 + threadIdx.x;
    if (t < E_TRAIN / 8) {
        int4 d0 = __ldg((const int4*)dst + 2 * t);
        int4 d1 = __ldg((const int4*)dst + 2 * t + 1);
        unsigned r0 = atomicAdd(&g_deg[d0.x], 1);
        unsigned r1 = atomicAdd(&g_deg[d0.y], 1);
        unsigned r2 = atomicAdd(&g_deg[d0.z], 1);
        unsigned r3 = atomicAdd(&g_deg[d0.w], 1);
        unsigned r4 = atomicAdd(&g_deg[d1.x], 1);
        unsigned r5 = atomicAdd(&g_deg[d1.y], 1);
        unsigned r6 = atomicAdd(&g_deg[d1.z], 1);
        unsigned r7 = atomicAdd(&g_deg[d1.w], 1);
        uint4 pk;
        pk.x = r0 | (r1 << 16);
        pk.y = r2 | (r3 << 16);
        pk.z = r4 | (r5 << 16);
        pk.w = r6 | (r7 << 16);
        ((uint4*)g_rank)[t] = pk;
    }
}

// ---- 3-phase multi-block exclusive scan -> rowptr/dinv ----------------------
__global__ __launch_bounds__(SCAN_B) void k_scan_local() {
    __shared__ int sh[SCAN_B];
    int t = threadIdx.x;
    int gid = blockIdx.x * SCAN_B + t;
    int d = (gid < N_NODES) ? g_deg[gid] : 0;
    int val = d;
    sh[t] = val;
    __syncthreads();
    for (int off = 1; off < SCAN_B; off <<= 1) {
        int v = (t >= off) ? sh[t - off] : 0;
        __syncthreads();
        val += v;
        sh[t] = val;
        __syncthreads();
    }
    if (gid < N_NODES) {
        g_rowptr[gid] = val - d;                 // local exclusive prefix
        g_dinv[gid]   = rsqrtf((float)(d + 1));  // +1 self loop
    }
    if (t == SCAN_B - 1) g_bsum[blockIdx.x] = val;
}

__global__ void k_scan_bsum() {
    __shared__ int sh[SCAN_NBLK];
    int t = threadIdx.x;   // 64 threads
    if (t < SCAN_NBLK) sh[t] = g_bsum[t];
    __syncthreads();
    if (t == 0) {
        int run = 0;
#pragma unroll
        for (int i = 0; i < SCAN_NBLK; i++) {
            int d = sh[i];
            sh[i] = run;
            run += d;
        }
        g_rowptr[N_NODES] = run;
    }
    __syncthreads();
    if (t < SCAN_NBLK) g_boff[t] = sh[t];
}

__global__ __launch_bounds__(SCAN_B) void k_scan_add() {
    int gid = blockIdx.x * SCAN_B + threadIdx.x;
    if (gid < N_NODES) g_rowptr[gid] += __ldg(g_boff + blockIdx.x);
}

// ---- atomic-free placement (4 edges/thread) ---------------------------------
__global__ void k_place(const int* __restrict__ src, const int* __restrict__ dst) {
    int t = blockIdx.x * 256 + threadIdx.x;
    if (t < E_TRAIN / 4) {
        int4 s0 = __ldg((const int4*)src + t);
        int4 d0 = __ldg((const int4*)dst + t);
        uint2 pk = __ldg((const uint2*)g_rank + t);
        int p0 = __ldg(g_rowptr + d0.x) + (pk.x & 0xffff);
        int p1 = __ldg(g_rowptr + d0.y) + (pk.x >> 16);
        int p2 = __ldg(g_rowptr + d0.z) + (pk.y & 0xffff);
        int p3 = __ldg(g_rowptr + d0.w) + (pk.y >> 16);
        g_esrc[p0] = (unsigned short)s0.x;
        g_esrc[p1] = (unsigned short)s0.y;
        g_esrc[p2] = (unsigned short)s0.z;
        g_esrc[p3] = (unsigned short)s0.w;
    }
}

// ---- scale bufA rows by dinv (layer 1 only) ---------------------------------
// thread -> uint2 (4 halves); 16 threads per node row.
__global__ __launch_bounds__(256) void k_scale() {
    int t = blockIdx.x * 256 + threadIdx.x;   // 3125 blocks exact: 800000 thr
    int node = t >> 4, q = t & 15;
    float di = __ldg(g_dinv + node);
    uint2 u = *(uint2*)&g_bufA[node * PAD + q * 4];
    __half2* hp = (__half2*)&u;
    float2 f0 = __half22float2(hp[0]);
    float2 f1 = __half22float2(hp[1]);
    __half2 o0 = __floats2half2_rn(f0.x * di, f0.y * di);
    __half2 o1 = __floats2half2_rn(f1.x * di, f1.y * di);
    uint2 st; st.x = *(unsigned*)&o0; st.y = *(unsigned*)&o1;
    *(uint2*)&g_bufA[node * PAD + q * 4] = st;
}

// ---- GEMM 1: bufA = fp16(x @ W1) UNSCALED, 32 nodes/block -------------------
__global__ __launch_bounds__(256) void k_gemm1(const float* __restrict__ x,
                                               const float* __restrict__ W1) {
    __shared__ float ws[F_IN][64];
    __shared__ float xs[32][F_IN + 2];
    int tid = threadIdx.x;
    int nodeBase = blockIdx.x * 32;                 // 1563 blocks (last partial)
    for (int t = tid; t < F_IN * 64; t += 256) {
        int k = t >> 6, j = t & 63;
        ws[k][j] = (j < HID) ? W1[k * HID + j] : 0.f;
    }
    for (int t = tid; t < 32 * F_IN; t += 256) {
        int n = t / F_IN, k = t % F_IN;
        int node = nodeBase + n;
        xs[n][k] = (node < N_NODES) ? x[node * F_IN + k] : 0.f;
    }
    __syncthreads();
    int n = tid >> 4, jq = tid & 15;
    int node0 = nodeBase + n;
    int node1 = nodeBase + n + 16;
    float4 accA = make_float4(0.f, 0.f, 0.f, 0.f);
    float4 accB = make_float4(0.f, 0.f, 0.f, 0.f);
#pragma unroll
    for (int k = 0; k < F_IN; k++) {
        float4 w = *(const float4*)&ws[k][jq * 4];
        float xv0 = xs[n][k];
        float xv1 = xs[n + 16][k];
        accA.x = fmaf(xv0, w.x, accA.x);
        accA.y = fmaf(xv0, w.y, accA.y);
        accA.z = fmaf(xv0, w.z, accA.z);
        accA.w = fmaf(xv0, w.w, accA.w);
        accB.x = fmaf(xv1, w.x, accB.x);
        accB.y = fmaf(xv1, w.y, accB.y);
        accB.z = fmaf(xv1, w.z, accB.z);
        accB.w = fmaf(xv1, w.w, accB.w);
    }
    if (node0 < N_NODES) {
        __half2 p0 = __floats2half2_rn(accA.x, accA.y);
        __half2 p1 = __floats2half2_rn(accA.z, accA.w);
        uint2 st; st.x = *(unsigned*)&p0; st.y = *(unsigned*)&p1;
        *(uint2*)&g_bufA[node0 * PAD + jq * 4] = st;
    }
    if (node1 < N_NODES) {
        __half2 p0 = __floats2half2_rn(accB.x, accB.y);
        __half2 p1 = __floats2half2_rn(accB.z, accB.w);
        uint2 st; st.x = *(unsigned*)&p0; st.y = *(unsigned*)&p1;
        *(uint2*)&g_bufA[node1 * PAD + jq * 4] = st;
    }
}

// ---- GEMM 2: bufA = fp16( dinv * (bufC @ W2) ), dinv folded at store --------
__global__ __launch_bounds__(256) void k_gemm2(const float* __restrict__ W2) {
    __shared__ float ws[HID][64];
    __shared__ float xs[32][HID + 2];
    int tid = threadIdx.x;
    int nodeBase = blockIdx.x * 32;
    for (int t = tid; t < HID * 64; t += 256) {
        int k = t >> 6, j = t & 63;
        ws[k][j] = W2[k * DOUT + j];
    }
    for (int t = tid; t < 32 * HID; t += 256) {
        int n = t / HID, k = t % HID;
        int node = nodeBase + n;
        xs[n][k] = (node < N_NODES) ? g_bufC[node * PAD + k] : 0.f;
    }
    __syncthreads();
    int n = tid >> 4, jq = tid & 15;
    int node0 = nodeBase + n;
    int node1 = nodeBase + n + 16;
    float4 accA = make_float4(0.f, 0.f, 0.f, 0.f);
    float4 accB = make_float4(0.f, 0.f, 0.f, 0.f);
#pragma unroll
    for (int k = 0; k < HID; k++) {
        float4 w = *(const float4*)&ws[k][jq * 4];
        float xv0 = xs[n][k];
        float xv1 = xs[n + 16][k];
        accA.x = fmaf(xv0, w.x, accA.x);
        accA.y = fmaf(xv0, w.y, accA.y);
        accA.z = fmaf(xv0, w.z, accA.z);
        accA.w = fmaf(xv0, w.w, accA.w);
        accB.x = fmaf(xv1, w.x, accB.x);
        accB.y = fmaf(xv1, w.y, accB.y);
        accB.z = fmaf(xv1, w.z, accB.z);
        accB.w = fmaf(xv1, w.w, accB.w);
    }
    if (node0 < N_NODES) {
        float di = __ldg(g_dinv + node0);
        __half2 p0 = __floats2half2_rn(accA.x * di, accA.y * di);
        __half2 p1 = __floats2half2_rn(accA.z * di, accA.w * di);
        uint2 st; st.x = *(unsigned*)&p0; st.y = *(unsigned*)&p1;
        *(uint2*)&g_bufA[node0 * PAD + jq * 4] = st;
    }
    if (node1 < N_NODES) {
        float di = __ldg(g_dinv + node1);
        __half2 p0 = __floats2half2_rn(accB.x * di, accB.y * di);
        __half2 p1 = __floats2half2_rn(accB.z * di, accB.w * di);
        uint2 st; st.x = *(unsigned*)&p0; st.y = *(unsigned*)&p1;
        *(uint2*)&g_bufA[node1 * PAD + jq * 4] = st;
    }
}

// ---- CSR aggregation + fused epilogue ---------------------------------------
// One warp per node. 4 edge-groups of 8 lanes; lane q owns 16B chunk q.
// Rows are PRE-SCALED hs = dinv[s]*h[s]: plain adds, 2 loads/edge.
template <int CH, int NB, bool RELU, bool FINAL>
__global__ __launch_bounds__(256) void k_agg(const float* __restrict__ bias) {
    int node = (blockIdx.x * 256 + threadIdx.x) >> 5;   // 6250 blocks exact
    int lane = threadIdx.x & 31;
    int g = lane >> 3, q = lane & 7;
    int rp = g_rowptr[node], re = g_rowptr[node + 1];
    float a0 = 0.f, a1 = 0.f, a2 = 0.f, a3 = 0.f;
    float a4 = 0.f, a5 = 0.f, a6 = 0.f, a7 = 0.f;
    const uint4* rows = (const uint4*)g_bufA;           // 8 uint4 per row
    const bool act = (CH == 8) || (q < CH);

#define ACCUM(U) do {                                                   \
        __half2* hp = (__half2*)&(U);                                   \
        float2 f0 = __half22float2(hp[0]);                              \
        float2 f1 = __half22float2(hp[1]);                              \
        float2 f2 = __half22float2(hp[2]);                              \
        float2 f3 = __half22float2(hp[3]);                              \
        a0 += f0.x; a1 += f0.y; a2 += f1.x; a3 += f1.y;                 \
        a4 += f2.x; a5 += f2.y; a6 += f3.x; a7 += f3.y;                 \
    } while (0)

    if (g == 0 && act) {                                // self loop
        uint4 u = __ldg(rows + node * 8 + q);
        ACCUM(u);
    }
    int e = rp + g;
    for (; e + 12 < re; e += 16) {
        int s0 = (int)__ldg(g_esrc + e);
        int s1 = (int)__ldg(g_esrc + e + 4);
        int s2 = (int)__ldg(g_esrc + e + 8);
        int s3 = (int)__ldg(g_esrc + e + 12);
        if (act) {
            uint4 u0 = __ldg(rows + s0 * 8 + q);
            uint4 u1 = __ldg(rows + s1 * 8 + q);
            uint4 u2 = __ldg(rows + s2 * 8 + q);
            uint4 u3 = __ldg(rows + s3 * 8 + q);
            ACCUM(u0); ACCUM(u1); ACCUM(u2); ACCUM(u3);
        }
    }
    for (; e + 4 < re; e += 8) {
        int s0 = (int)__ldg(g_esrc + e);
        int s1 = (int)__ldg(g_esrc + e + 4);
        if (act) {
            uint4 u0 = __ldg(rows + s0 * 8 + q);
            uint4 u1 = __ldg(rows + s1 * 8 + q);
            ACCUM(u0); ACCUM(u1);
        }
    }
    if (e < re) {
        int s0 = (int)__ldg(g_esrc + e);
        if (act) {
            uint4 u0 = __ldg(rows + s0 * 8 + q);
            ACCUM(u0);
        }
    }
#undef ACCUM

#define RED(off) do {                                                   \
        a0 += __shfl_xor_sync(0xffffffffu, a0, off);                    \
        a1 += __shfl_xor_sync(0xffffffffu, a1, off);                    \
        a2 += __shfl_xor_sync(0xffffffffu, a2, off);                    \
        a3 += __shfl_xor_sync(0xffffffffu, a3, off);                    \
        a4 += __shfl_xor_sync(0xffffffffu, a4, off);                    \
        a5 += __shfl_xor_sync(0xffffffffu, a5, off);                    \
        a6 += __shfl_xor_sync(0xffffffffu, a6, off);                    \
        a7 += __shfl_xor_sync(0xffffffffu, a7, off);                    \
    } while (0)
    RED(8);
    RED(16);
#undef RED

    if (g == 0 && act) {
        float di = g_dinv[node];
        int j0 = q * 8;
        float acc[8] = {a0, a1, a2, a3, a4, a5, a6, a7};
        float v[8];
#pragma unroll
        for (int i = 0; i < 8; i++) {
            int j = j0 + i;
            float bv = (j < NB) ? __ldg(bias + j) : 0.f;
            float r = fmaf(di, acc[i], bv);
            if (RELU) r = fmaxf(r, 0.f);
            v[i] = r;
        }
        if (FINAL) {
            __half2 h0 = __floats2half2_rn(v[0], v[1]);
            __half2 h1 = __floats2half2_rn(v[2], v[3]);
            __half2 h2 = __floats2half2_rn(v[4], v[5]);
            __half2 h3 = __floats2half2_rn(v[6], v[7]);
            uint4 st;
            st.x = *(unsigned*)&h0; st.y = *(unsigned*)&h1;
            st.z = *(unsigned*)&h2; st.w = *(unsigned*)&h3;
            *(uint4*)&g_z[node * PAD + j0] = st;
        } else {
            float4 r0 = make_float4(v[0], v[1], v[2], v[3]);
            float4 r1 = make_float4(v[4], v[5], v[6], v[7]);
            *(float4*)(g_bufC + node * PAD + j0)     = r0;
            *(float4*)(g_bufC + node * PAD + j0 + 4) = r1;
        }
    }
}

// ---- decode: logits[e] = dot64(z[a], z[b]), z fp16 --------------------------
__global__ void k_decode(const int* __restrict__ pos,
                         const int* __restrict__ neg,
                         float* __restrict__ out) {
    int gt = blockIdx.x * 256 + threadIdx.x;   // 12500 blocks exact
    int e = gt >> 3;
    int j = gt & 7;
    int a, b;
    if (e < EP) { a = pos[e];        b = pos[EP + e]; }
    else        { int e2 = e - EP;  a = neg[e2];     b = neg[EN + e2]; }
    uint4 ua = __ldg((const uint4*)(g_z + a * PAD) + j);
    uint4 ub = __ldg((const uint4*)(g_z + b * PAD) + j);
    __half2* ha = (__half2*)&ua;
    __half2* hb = (__half2*)&ub;
    float s = 0.f;
#pragma unroll
    for (int i = 0; i < 4; i++) {
        float2 fa = __half22float2(ha[i]);
        float2 fb = __half22float2(hb[i]);
        s = fmaf(fa.x, fb.x, s);
        s = fmaf(fa.y, fb.y, s);
    }
#pragma unroll
    for (int o = 4; o; o >>= 1) s += __shfl_xor_sync(0xffffffffu, s, o);
    if (j == 0) out[e] = s;
}

// ---------------------------------------------------------------------------
extern "C" void kernel_launch(void* const* d_in, const int* in_sizes, int n_in,
                              void* d_out, int out_size) {
    const float* x   = (const float*)d_in[0];
    const int*   tr  = (const int*)d_in[1];
    const int*   pos = (const int*)d_in[2];
    const int*   neg = (const int*)d_in[3];
    const float* W1  = (const float*)d_in[4];
    const float* b1  = (const float*)d_in[5];
    const float* W2  = (const float*)d_in[6];
    const float* b2  = (const float*)d_in[7];
    float* out = (float*)d_out;

    const int* src = tr;
    const int* dst = tr + E_TRAIN;

    static cudaStream_t sB = nullptr;
    static cudaEvent_t  evStart = nullptr, evScan = nullptr, evG1 = nullptr;
    if (sB == nullptr) {
        cudaStreamCreateWithFlags(&sB, cudaStreamNonBlocking);
        cudaEventCreateWithFlags(&evStart, cudaEventDisableTiming);
        cudaEventCreateWithFlags(&evScan,  cudaEventDisableTiming);
        cudaEventCreateWithFlags(&evG1,    cudaEventDisableTiming);
    }

    // Fork at t=0: gemm1 (unscaled -> no build dependency) on stream B.
    cudaEventRecord(evStart, 0);
    cudaStreamWaitEvent(sB, evStart, 0);
    k_gemm1<<<(N_NODES + 31) / 32, 256, 0, sB>>>(x, W1);

    // CSR build on default stream, concurrent with gemm1.
    k_zero<<<(N_NODES + 255) / 256, 256>>>();
    k_count<<<(E_TRAIN / 8 + 255) / 256, 256>>>(dst);
    k_scan_local<<<SCAN_NBLK, SCAN_B>>>();
    k_scan_bsum<<<1, 64>>>();
    k_scan_add<<<SCAN_NBLK, SCAN_B>>>();
    cudaEventRecord(evScan, 0);          // dinv ready

    // Stream B: scale bufA by dinv (needs gemm1 done + scan done),
    // concurrent with place on the default stream.
    cudaStreamWaitEvent(sB, evScan, 0);
    k_scale<<<N_NODES * 16 / 256, 256, 0, sB>>>();
    cudaEventRecord(evG1, sB);

    k_place<<<(E_TRAIN / 4 + 255) / 256, 256>>>(src, dst);

    // Join, then layer 1 aggregation.
    cudaStreamWaitEvent(0, evG1, 0);
    k_agg<7, HID, true, false><<<N_NODES * 32 / 256, 256>>>(b1);

    // layer 2
    k_gemm2<<<(N_NODES + 31) / 32, 256>>>(W2);
    k_agg<8, DOUT, false, true><<<N_NODES * 32 / 256, 256>>>(b2);

    // decode
    k_decode<<<(EP + EN) * 8 / 256, 256>>>(pos, neg, out);
}